// round 8
// baseline (speedup 1.0000x reference)
#include <cuda_runtime.h>
#include <cuda_bf16.h>

#define NN 100000
#define NE 1600000
#define CC 128
#define HB 65536
#define EPS 1e-5
#define PBLK 148

// ---------------- scratch (static __device__ — no allocation allowed) -------
__device__ float g_aggx[NN * CC];
__device__ float g_aggp[NN * 3];
__device__ float g_h0[NN * CC];
__device__ float g_h1[NN * CC];
__device__ float g_pool[NN * CC];
__device__ int   g_rowD[NN + 1];
__device__ int   g_rowS[NN + 1];
__device__ int   g_curD[NN];
__device__ int   g_curS[NN];
__device__ int   g_colD[NE];
__device__ float g_ewD[NE];
__device__ int   g_colS[2 * NE];
__device__ float g_score[NN];
__device__ unsigned g_key[NN];
__device__ int   g_rank[NN];
__device__ int   g_arank[NN];
__device__ unsigned char g_mis[NN];
__device__ unsigned char g_sel[NN];
__device__ int   g_cluster[NN];
__device__ int   g_hist[HB];
__device__ int   g_base[HB + 1];
__device__ int   g_bcur[HB];
__device__ unsigned g_bkey[NN];
__device__ double g_sum[CC];
__device__ double g_sq[CC];
__device__ float g_bns[CC];
__device__ float g_bnt[CC];
__device__ int   g_part[160];       // scan partials
__device__ int   g_fr[2][NN];       // MIS frontiers
__device__ int   g_fc[2];           // frontier counts
__device__ unsigned g_barGen;
__device__ unsigned g_barCnt;

// ---------------- packed fp32x2 FMA (exact fp32, 2x throughput) -------------
__device__ __forceinline__ void fma2(unsigned long long& d, unsigned long long a,
                                     unsigned long long b) {
    asm("fma.rn.f32x2 %0, %1, %2, %3;" : "=l"(d) : "l"(a), "l"(b), "l"(d));
}

// ---------------- CSR construction -----------------------------------------
__global__ void kCountDeg(const int* __restrict__ ei) {
    int e = blockIdx.x * blockDim.x + threadIdx.x;
    if (e >= NE) return;
    int s = ei[e], d = ei[NE + e];
    atomicAdd(&g_curD[d], 1);
    atomicAdd(&g_curS[s], 1);
    atomicAdd(&g_curS[d], 1);
}

// ---------------- hierarchical exclusive scan -------------------------------
__global__ void kScanA(const int* __restrict__ in, int* __restrict__ out, int n) {
    __shared__ int sh[256];
    int b = blockIdx.x, t = threadIdx.x;
    int base = b * 1024 + t * 4;
    int v0 = (base + 0 < n) ? in[base + 0] : 0;
    int v1 = (base + 1 < n) ? in[base + 1] : 0;
    int v2 = (base + 2 < n) ? in[base + 2] : 0;
    int v3 = (base + 3 < n) ? in[base + 3] : 0;
    int s = v0 + v1 + v2 + v3;
    sh[t] = s;
    __syncthreads();
    for (int off = 1; off < 256; off <<= 1) {
        int x = (t >= off) ? sh[t - off] : 0;
        __syncthreads();
        sh[t] += x;
        __syncthreads();
    }
    int excl = sh[t] - s;
    if (t == 255) g_part[b] = sh[255];
    int run = excl;
    if (base + 0 < n) out[base + 0] = run; run += v0;
    if (base + 1 < n) out[base + 1] = run; run += v1;
    if (base + 2 < n) out[base + 2] = run; run += v2;
    if (base + 3 < n) out[base + 3] = run;
}

__global__ void kScanB(int m) {
    __shared__ int sh[128];
    int t = threadIdx.x;
    int v = (t < m) ? g_part[t] : 0;
    sh[t] = v;
    __syncthreads();
    for (int off = 1; off < 128; off <<= 1) {
        int x = (t >= off) ? sh[t - off] : 0;
        __syncthreads();
        sh[t] += x;
        __syncthreads();
    }
    if (t < m) g_part[t] = sh[t] - v;
    if (t == 0) g_part[m] = sh[m - 1 < 0 ? 0 : m - 1];
}

__global__ void kScanC(int* __restrict__ out, int n, int m) {
    int i = blockIdx.x * blockDim.x + threadIdx.x;
    if (i < n) out[i] += g_part[i >> 10];
    else if (i == n) out[n] = g_part[m];
}

__global__ void kInitCur() {
    int i = blockIdx.x * blockDim.x + threadIdx.x;
    if (i >= NN) return;
    g_curD[i] = g_rowD[i];
    g_curS[i] = g_rowS[i];
}

__global__ void kFill(const int* __restrict__ ei, const float* __restrict__ ew) {
    int e = blockIdx.x * blockDim.x + threadIdx.x;
    if (e >= NE) return;
    int s = ei[e], d = ei[NE + e];
    float w = ew[e];
    int p = atomicAdd(&g_curD[d], 1);
    g_colD[p] = s;
    g_ewD[p] = w;
    int q = atomicAdd(&g_curS[s], 1);
    g_colS[q] = d;
    int r = atomicAdd(&g_curS[d], 1);
    g_colS[r] = s;
}

// ---------------- position aggregation (layer-invariant) --------------------
__global__ void kAggP(const int* __restrict__ ei, const float* __restrict__ ew,
                      const float* __restrict__ pos) {
    int e = blockIdx.x * blockDim.x + threadIdx.x;
    if (e >= NE) return;
    int s = ei[e], d = ei[NE + e];
    float w = ew[e];
#pragma unroll
    for (int p = 0; p < 3; p++)
        atomicAdd(&g_aggp[d * 3 + p], w * (pos[s * 3 + p] - pos[d * 3 + p]));
}

// ---------------- feature aggregation: warp per node, float4 lanes ----------
__global__ void kAggX(const float* __restrict__ x) {
    int u = blockIdx.x * 8 + (threadIdx.x >> 5);
    int lane = threadIdx.x & 31;
    if (u >= NN) return;
    int b = g_rowD[u], e = g_rowD[u + 1];
    float4 acc = make_float4(0.f, 0.f, 0.f, 0.f);
    int t = b;
    for (; t + 1 < e; t += 2) {
        int s0 = g_colD[t], s1 = g_colD[t + 1];
        float w0 = g_ewD[t], w1 = g_ewD[t + 1];
        float4 v0 = __ldg(&((const float4*)x)[s0 * 32 + lane]);
        float4 v1 = __ldg(&((const float4*)x)[s1 * 32 + lane]);
        acc.x += w0 * v0.x + w1 * v1.x;
        acc.y += w0 * v0.y + w1 * v1.y;
        acc.z += w0 * v0.z + w1 * v1.z;
        acc.w += w0 * v0.w + w1 * v1.w;
    }
    if (t < e) {
        int s0 = g_colD[t];
        float w0 = g_ewD[t];
        float4 v0 = __ldg(&((const float4*)x)[s0 * 32 + lane]);
        acc.x += w0 * v0.x; acc.y += w0 * v0.y; acc.z += w0 * v0.z; acc.w += w0 * v0.w;
    }
    ((float4*)g_aggx)[u * 32 + lane] = acc;
}

// ---------------- fused dual-GEMM via packed f32x2 FMA ----------------------
// 128x128 tile, 8x8 per thread; rows paired into u64 accumulators; B stored
// duplicated in smem so each LDS.64 yields {b,b}.
__global__ __launch_bounds__(256, 2)
void kGemm(const float* __restrict__ A1, const float* __restrict__ A2,
           const float* __restrict__ W1, const float* __restrict__ W2,
           const float* __restrict__ Wp, const float* __restrict__ bias,
           float* __restrict__ out) {
    __shared__ float As[16][132];    // [k][row]
    __shared__ float Bsd[16][256];   // [k][2*col] duplicated
    int tid = threadIdx.x;
    int tx = tid & 15, ty = tid >> 4;
    int rowBase = blockIdx.x * 128;
    unsigned long long acc2[4][8];
    const float zz[2] = {0.f, 0.f};
    unsigned long long z = *(const unsigned long long*)zz;
#pragma unroll
    for (int p = 0; p < 4; p++)
#pragma unroll
        for (int j = 0; j < 8; j++) acc2[p][j] = z;

    for (int m = 0; m < 2; m++) {
        const float* A = m ? A2 : A1;
        const float* W = m ? W2 : W1;
        for (int kb = 0; kb < 128; kb += 16) {
            // A tile transposed: [k][row]
#pragma unroll
            for (int i = 0; i < 2; i++) {
                int idx = tid + i * 256;
                int r = idx >> 2;
                int k4 = idx & 3;
                int row = rowBase + r;
                float4 v = (row < NN) ? ((const float4*)A)[row * 32 + (kb >> 2) + k4]
                                      : make_float4(0.f, 0.f, 0.f, 0.f);
                As[k4 * 4 + 0][r] = v.x;
                As[k4 * 4 + 1][r] = v.y;
                As[k4 * 4 + 2][r] = v.z;
                As[k4 * 4 + 3][r] = v.w;
            }
            // B tile duplicated: Bsd[k][2c]=Bsd[k][2c+1]=W[k][c]
#pragma unroll
            for (int i = 0; i < 2; i++) {
                int idx = tid + i * 256;
                int r = idx >> 5;
                int c4 = idx & 31;
                float4 v = ((const float4*)W)[(kb + r) * 32 + c4];
                ((float4*)&Bsd[r][c4 * 8])[0] = make_float4(v.x, v.x, v.y, v.y);
                ((float4*)&Bsd[r][c4 * 8])[1] = make_float4(v.z, v.z, v.w, v.w);
            }
            __syncthreads();
#pragma unroll
            for (int k = 0; k < 16; k++) {
                ulonglong2 aA = *(const ulonglong2*)&As[k][ty * 8];
                ulonglong2 aB = *(const ulonglong2*)&As[k][ty * 8 + 4];
                unsigned long long ap[4] = {aA.x, aA.y, aB.x, aB.y};
                ulonglong2 b0 = *(const ulonglong2*)&Bsd[k][tx * 16];
                ulonglong2 b1 = *(const ulonglong2*)&Bsd[k][tx * 16 + 4];
                ulonglong2 b2 = *(const ulonglong2*)&Bsd[k][tx * 16 + 8];
                ulonglong2 b3 = *(const ulonglong2*)&Bsd[k][tx * 16 + 12];
                unsigned long long bd[8] = {b0.x, b0.y, b1.x, b1.y,
                                            b2.x, b2.y, b3.x, b3.y};
#pragma unroll
                for (int p = 0; p < 4; p++)
#pragma unroll
                    for (int j = 0; j < 8; j++) fma2(acc2[p][j], ap[p], bd[j]);
            }
            __syncthreads();
        }
    }
#pragma unroll
    for (int p = 0; p < 4; p++) {
        int r0 = rowBase + ty * 8 + 2 * p;
        int r1 = r0 + 1;
        float q00 = 0, q01 = 0, q02 = 0, q10 = 0, q11 = 0, q12 = 0;
        if (r0 < NN) { q00 = g_aggp[r0 * 3]; q01 = g_aggp[r0 * 3 + 1]; q02 = g_aggp[r0 * 3 + 2]; }
        if (r1 < NN) { q10 = g_aggp[r1 * 3]; q11 = g_aggp[r1 * 3 + 1]; q12 = g_aggp[r1 * 3 + 2]; }
#pragma unroll
        for (int j = 0; j < 8; j++) {
            int col = tx * 8 + j;
            float2 f2 = *(float2*)&acc2[p][j];
            float wp0 = Wp[col], wp1 = Wp[CC + col], wp2 = Wp[2 * CC + col], bb = bias[col];
            if (r0 < NN) out[r0 * CC + col] = f2.x + q00 * wp0 + q01 * wp1 + q02 * wp2 + bb;
            if (r1 < NN) out[r1 * CC + col] = f2.y + q10 * wp0 + q11 * wp1 + q12 * wp2 + bb;
        }
    }
}

// ---------------- batch-norm ------------------------------------------------
__global__ void kColSum(const float* __restrict__ pre) {
    int c = threadIdx.x;
    int rowBase = blockIdx.x * 512;
    int rowEnd = min(rowBase + 512, NN);
    float s = 0.f, q = 0.f;
    for (int r = rowBase; r < rowEnd; r++) {
        float v = pre[r * CC + c];
        s += v;
        q += v * v;
    }
    atomicAdd(&g_sum[c], (double)s);
    atomicAdd(&g_sq[c], (double)q);
}

__global__ void kBnFinal(const float* __restrict__ g, const float* __restrict__ be) {
    int c = threadIdx.x;
    double mu = g_sum[c] / (double)NN;
    double var = g_sq[c] / (double)NN - mu * mu;
    float sc = (float)((double)g[c] / sqrt(var + (double)EPS));
    g_bns[c] = sc;
    g_bnt[c] = be[c] - (float)mu * sc;
}

__global__ void kBnRelu(float* __restrict__ pre) {
    int idx = blockIdx.x * blockDim.x + threadIdx.x;
    if (idx >= NN * CC) return;
    int c = idx & (CC - 1);
    float v = pre[idx] * g_bns[c] + g_bnt[c];
    pre[idx] = v > 0.f ? v : 0.f;
}

// ---------------- score + ranking -------------------------------------------
__global__ void kScore(const float* __restrict__ h, const float* __restrict__ w) {
    int gw = (blockIdx.x * blockDim.x + threadIdx.x) >> 5;
    int lane = threadIdx.x & 31;
    if (gw >= NN) return;
    float acc = 0.f;
    for (int c = lane; c < CC; c += 32) acc += h[gw * CC + c] * w[c];
#pragma unroll
    for (int o = 16; o; o >>= 1) acc += __shfl_down_sync(0xffffffffu, acc, o);
    if (lane == 0) g_score[gw] = acc;
}

__global__ void kKeyHist() {
    int i = blockIdx.x * blockDim.x + threadIdx.x;
    if (i >= NN) return;
    unsigned u = __float_as_uint(g_score[i]);
    u = (u & 0x80000000u) ? ~u : (u | 0x80000000u);
    g_key[i] = u;
    atomicAdd(&g_hist[u >> 16], 1);
}

__global__ void kBucketFill() {
    int i = blockIdx.x * blockDim.x + threadIdx.x;
    if (i >= NN) return;
    unsigned k = g_key[i];
    int hi = k >> 16;
    int p = g_base[hi] + atomicAdd(&g_bcur[hi], 1);
    g_bkey[p] = k;
}

__global__ void kRank() {
    int i = blockIdx.x * blockDim.x + threadIdx.x;
    if (i >= NN) return;
    unsigned k = g_key[i];
    int hi = k >> 16;
    int s = g_base[hi], e = g_base[hi + 1];
    int c = 0;
    for (int t = s; t < e; t++) c += (g_bkey[t] < k) ? 1 : 0;
    g_rank[i] = 1 + s + c;
}

// ---------------- MIS: persistent kernel with frontier ----------------------
__global__ void kMisInit() {
    int i = blockIdx.x * blockDim.x + threadIdx.x;
    if (i >= NN) return;
    g_arank[i] = g_rank[i];
    g_fr[0][i] = i;
    if (i == 0) { g_fc[0] = NN; g_fc[1] = 0; }
}

__device__ __forceinline__ void gridBar() {
    __syncthreads();
    if (threadIdx.x == 0) {
        __threadfence();
        unsigned gen = g_barGen;
        unsigned t = atomicAdd(&g_barCnt, 1);
        if (t == PBLK - 1) {
            g_barCnt = 0;
            __threadfence();
            atomicAdd(&g_barGen, 1);
        } else {
            while (*(volatile unsigned*)&g_barGen == gen) {}
            __threadfence();
        }
    }
    __syncthreads();
}

__global__ void kMisPersist() {
    int tid = threadIdx.x;
    int gw = (blockIdx.x * 256 + tid) >> 5;
    int lane = tid & 31;
    const int nw = (PBLK * 256) >> 5;
    int p = 0;
    for (int it = 0; it < 32; it++) {
        int fc = g_fc[p];
        if (fc == 0) break;   // fixpoint: remaining iterations are no-ops
        // phase A: compute sel over frontier
        for (int i = gw; i < fc; i += nw) {
            int u = g_fr[p][i];
            int au = g_arank[u];
            int b = g_rowS[u], e = g_rowS[u + 1];
            int nmax = -1;
            for (int t = b + lane; t < e; t += 32)
                nmax = max(nmax, g_arank[g_colS[t]]);
#pragma unroll
            for (int o = 16; o; o >>= 1)
                nmax = max(nmax, __shfl_xor_sync(0xffffffffu, nmax, o));
            if (lane == 0) g_sel[u] = (au > nmax) ? 1 : 0;
        }
        gridBar();
        // phase B: commit, drop neighbors, build next frontier
        for (int i = gw; i < fc; i += nw) {
            int u = g_fr[p][i];
            if (g_sel[u]) {
                if (lane == 0) { g_mis[u] = 1; g_arank[u] = -1; }
                continue;
            }
            int b = g_rowS[u], e = g_rowS[u + 1];
            int f = 0;
            for (int t = b + lane; t < e; t += 32) f |= g_sel[g_colS[t]];
            unsigned any = __ballot_sync(0xffffffffu, f != 0);
            if (lane == 0) {
                if (any) g_arank[u] = -1;
                else {
                    int pos = atomicAdd(&g_fc[1 - p], 1);
                    g_fr[1 - p][pos] = u;
                }
            }
        }
        gridBar();
        if (blockIdx.x == 0 && tid == 0) g_fc[p] = 0;
        p ^= 1;
    }
}

__global__ void kCluster() {
    int u = (blockIdx.x * blockDim.x + threadIdx.x) >> 5;
    int lane = threadIdx.x & 31;
    if (u >= NN) return;
    int b = g_rowS[u], e = g_rowS[u + 1];
    int bm = -1, arg = -1;
    for (int t = b + lane; t < e; t += 32) {
        int j = g_colS[t];
        if (g_mis[j]) {
            int r = g_rank[j];
            if (r > bm) { bm = r; arg = j; }
        }
    }
#pragma unroll
    for (int o = 16; o; o >>= 1) {
        int obm = __shfl_down_sync(0xffffffffu, bm, o);
        int oarg = __shfl_down_sync(0xffffffffu, arg, o);
        if (obm > bm) { bm = obm; arg = oarg; }
    }
    if (lane == 0) g_cluster[u] = g_mis[u] ? u : (arg >= 0 ? arg : u);
}

// ---------------- pooling + outputs -----------------------------------------
__global__ void kPoolScatter() {
    int idx = blockIdx.x * blockDim.x + threadIdx.x;
    if (idx >= NN * CC) return;
    int i = idx >> 7, c = idx & 127;
    float v = g_h1[idx];
    int t = g_cluster[i];
    atomicMax((int*)&g_pool[t * CC + c], __float_as_int(v));
}

__global__ void kOutX(float* __restrict__ out, int osz) {
    int idx = blockIdx.x * blockDim.x + threadIdx.x;
    if (idx >= NN * CC) return;
    float v = g_mis[idx >> 7] ? g_pool[idx] : 0.f;
    if (idx < osz) out[idx] = v;
}

__global__ void kOutEdge(const int* __restrict__ ei, float* __restrict__ out, int osz) {
    int e = blockIdx.x * blockDim.x + threadIdx.x;
    if (e >= NE) return;
    int o1 = NN * CC + e, o2 = NN * CC + NE + e;
    if (o1 < osz) out[o1] = (float)g_cluster[ei[e]];
    if (o2 < osz) out[o2] = (float)g_cluster[ei[NE + e]];
}

__global__ void kOutTail(const float* __restrict__ ew, const float* __restrict__ pos,
                         const int* __restrict__ batch, float* __restrict__ out, int osz) {
    int idx = blockIdx.x * blockDim.x + threadIdx.x;
    const int b0 = NN * CC + 2 * NE;
    const int b1 = b0 + NE;
    const int b2 = b1 + NN * 3;
    const int b3 = b2 + NN;
    if (idx < NE && b0 + idx < osz) out[b0 + idx] = ew[idx];
    if (idx < NN * 3 && b1 + idx < osz) out[b1 + idx] = g_mis[idx / 3] ? pos[idx] : 0.f;
    if (idx < NN && b2 + idx < osz) out[b2 + idx] = (float)batch[idx];
    if (idx < NN && b3 + idx < osz) out[b3 + idx] = g_mis[idx] ? 1.f : 0.f;
}

// ---------------- helper ----------------------------------------------------
static void runScan(const int* in, int* out, int n) {
    int m = (n + 1023) / 1024;
    kScanA<<<m, 256>>>(in, out, n);
    kScanB<<<1, 128>>>(m);
    kScanC<<<(n + 256) / 256, 256>>>(out, n, m);
}

// ---------------- launch ----------------------------------------------------
extern "C" void kernel_launch(void* const* d_in, const int* in_sizes, int n_in,
                              void* d_out, int out_size) {
    const float* x     = (const float*)d_in[0];
    const int*   ei    = (const int*)d_in[1];
    const float* ew    = (const float*)d_in[2];
    const float* pos   = (const float*)d_in[3];
    const int*   batch = (const int*)d_in[4];
    const float* Wr0 = (const float*)d_in[5];
    const float* Wm0 = (const float*)d_in[6];
    const float* Wp0 = (const float*)d_in[7];
    const float* b0  = (const float*)d_in[8];
    const float* g0  = (const float*)d_in[9];
    const float* be0 = (const float*)d_in[10];
    const float* Wr1 = (const float*)d_in[11];
    const float* Wm1 = (const float*)d_in[12];
    const float* Wp1 = (const float*)d_in[13];
    const float* b1  = (const float*)d_in[14];
    const float* g1  = (const float*)d_in[15];
    const float* be1 = (const float*)d_in[16];
    const float* wsc = (const float*)d_in[17];
    float* out = (float*)d_out;

    void *p_curD, *p_curS, *p_rowD, *p_rowS, *p_aggp, *p_hist, *p_base, *p_bcur,
         *p_mis, *p_sel, *p_pool, *p_sum, *p_sq, *p_h0, *p_h1, *p_aggx,
         *p_barG, *p_barC;
    cudaGetSymbolAddress(&p_curD, g_curD);
    cudaGetSymbolAddress(&p_curS, g_curS);
    cudaGetSymbolAddress(&p_rowD, g_rowD);
    cudaGetSymbolAddress(&p_rowS, g_rowS);
    cudaGetSymbolAddress(&p_aggp, g_aggp);
    cudaGetSymbolAddress(&p_hist, g_hist);
    cudaGetSymbolAddress(&p_base, g_base);
    cudaGetSymbolAddress(&p_bcur, g_bcur);
    cudaGetSymbolAddress(&p_mis,  g_mis);
    cudaGetSymbolAddress(&p_sel,  g_sel);
    cudaGetSymbolAddress(&p_pool, g_pool);
    cudaGetSymbolAddress(&p_sum,  g_sum);
    cudaGetSymbolAddress(&p_sq,   g_sq);
    cudaGetSymbolAddress(&p_h0,   g_h0);
    cudaGetSymbolAddress(&p_h1,   g_h1);
    cudaGetSymbolAddress(&p_aggx, g_aggx);
    cudaGetSymbolAddress(&p_barG, g_barGen);
    cudaGetSymbolAddress(&p_barC, g_barCnt);
    float* h0 = (float*)p_h0;
    float* h1 = (float*)p_h1;

    const int EB = (NE + 255) / 256;
    const int NB = (NN + 255) / 256;
    const int WB = (NN * 32 + 255) / 256;
    const int XB = (NN * CC + 255) / 256;
    const int GB = (NN + 127) / 128;
    const int AB = (NN + 7) / 8;

    // ---- CSR build ----
    cudaMemsetAsync(p_curD, 0, NN * sizeof(int));
    cudaMemsetAsync(p_curS, 0, NN * sizeof(int));
    kCountDeg<<<EB, 256>>>(ei);
    runScan((const int*)p_curD, (int*)p_rowD, NN);
    runScan((const int*)p_curS, (int*)p_rowS, NN);
    kInitCur<<<NB, 256>>>();
    kFill<<<EB, 256>>>(ei, ew);

    // ---- pos aggregation ----
    cudaMemsetAsync(p_aggp, 0, NN * 3 * sizeof(float));
    kAggP<<<EB, 256>>>(ei, ew, pos);

    // ---- layer 0 ----
    kAggX<<<AB, 256>>>(x);
    kGemm<<<GB, 256>>>(x, (const float*)p_aggx, Wr0, Wm0, Wp0, b0, h0);
    cudaMemsetAsync(p_sum, 0, CC * sizeof(double));
    cudaMemsetAsync(p_sq, 0, CC * sizeof(double));
    kColSum<<<(NN + 511) / 512, CC>>>(h0);
    kBnFinal<<<1, CC>>>(g0, be0);
    kBnRelu<<<XB, 256>>>(h0);

    // ---- layer 1 ----
    kAggX<<<AB, 256>>>(h0);
    kGemm<<<GB, 256>>>(h0, (const float*)p_aggx, Wr1, Wm1, Wp1, b1, h1);
    cudaMemsetAsync(p_sum, 0, CC * sizeof(double));
    cudaMemsetAsync(p_sq, 0, CC * sizeof(double));
    kColSum<<<(NN + 511) / 512, CC>>>(h1);
    kBnFinal<<<1, CC>>>(g1, be1);
    kBnRelu<<<XB, 256>>>(h1);

    // ---- score -> unique ranks ----
    kScore<<<(NN * 32 + 255) / 256, 256>>>(h1, wsc);
    cudaMemsetAsync(p_hist, 0, HB * sizeof(int));
    kKeyHist<<<NB, 256>>>();
    runScan((const int*)p_hist, (int*)p_base, HB);
    cudaMemsetAsync(p_bcur, 0, HB * sizeof(int));
    kBucketFill<<<NB, 256>>>();
    kRank<<<NB, 256>>>();

    // ---- MIS (persistent kernel, frontier-compacted) ----
    cudaMemsetAsync(p_mis, 0, NN);
    cudaMemsetAsync(p_sel, 0, NN);
    cudaMemsetAsync(p_barG, 0, sizeof(unsigned));
    cudaMemsetAsync(p_barC, 0, sizeof(unsigned));
    kMisInit<<<NB, 256>>>();
    kMisPersist<<<PBLK, 256>>>();
    kCluster<<<WB, 256>>>();

    // ---- pooling + outputs ----
    cudaMemsetAsync(p_pool, 0, NN * CC * sizeof(float));
    kPoolScatter<<<XB, 256>>>();
    kOutX<<<XB, 256>>>(out, out_size);
    kOutEdge<<<EB, 256>>>(ei, out, out_size);
    kOutTail<<<EB, 256>>>(ew, pos, batch, out, out_size);
}

// round 15
// speedup vs baseline: 1.4370x; 1.4370x over previous
#include <cuda_runtime.h>
#include <cuda_bf16.h>

#define NN 100000
#define NE 1600000
#define CC 128
#define HB 65536
#define EPS 1e-5
#define PBLK 148

// ---------------- scratch (static __device__ — no allocation allowed) -------
__device__ float g_aggx[NN * CC];
__device__ float g_aggp[NN * 3];
__device__ float g_h0[NN * CC];
__device__ float g_h1[NN * CC];
__device__ float g_pool[NN * CC];
__device__ int   g_rowD[NN + 1];
__device__ int   g_rowS[NN + 1];
__device__ int   g_curD[NN];
__device__ int   g_curS[NN];
__device__ int   g_colD[NE];
__device__ float g_ewD[NE];
__device__ int   g_colS[2 * NE];
__device__ float g_score[NN];
__device__ unsigned g_key[NN];
__device__ int   g_rank[NN];
__device__ int   g_arank[NN];
__device__ unsigned char g_mis[NN];
__device__ unsigned char g_sel[NN];
__device__ int   g_cluster[NN];
__device__ int   g_hist[HB];
__device__ int   g_base[HB + 1];
__device__ int   g_bcur[HB];
__device__ unsigned g_bkey[NN];
__device__ double g_sum[CC];
__device__ double g_sq[CC];
__device__ float g_bns[CC];
__device__ float g_bnt[CC];
__device__ int   g_part[160];       // scan partials
__device__ int   g_fr[2][NN];       // MIS frontiers
__device__ int   g_fc[2];           // frontier counts
__device__ unsigned g_barGen;
__device__ unsigned g_barCnt;

// ---------------- CSR construction -----------------------------------------
__global__ void kCountDeg(const int* __restrict__ ei) {
    int e = blockIdx.x * blockDim.x + threadIdx.x;
    if (e >= NE) return;
    int s = ei[e], d = ei[NE + e];
    atomicAdd(&g_curD[d], 1);
    atomicAdd(&g_curS[s], 1);
    atomicAdd(&g_curS[d], 1);
}

// ---------------- hierarchical exclusive scan -------------------------------
__global__ void kScanA(const int* __restrict__ in, int* __restrict__ out, int n) {
    __shared__ int sh[256];
    int b = blockIdx.x, t = threadIdx.x;
    int base = b * 1024 + t * 4;
    int v0 = (base + 0 < n) ? in[base + 0] : 0;
    int v1 = (base + 1 < n) ? in[base + 1] : 0;
    int v2 = (base + 2 < n) ? in[base + 2] : 0;
    int v3 = (base + 3 < n) ? in[base + 3] : 0;
    int s = v0 + v1 + v2 + v3;
    sh[t] = s;
    __syncthreads();
    for (int off = 1; off < 256; off <<= 1) {
        int x = (t >= off) ? sh[t - off] : 0;
        __syncthreads();
        sh[t] += x;
        __syncthreads();
    }
    int excl = sh[t] - s;
    if (t == 255) g_part[b] = sh[255];
    int run = excl;
    if (base + 0 < n) out[base + 0] = run; run += v0;
    if (base + 1 < n) out[base + 1] = run; run += v1;
    if (base + 2 < n) out[base + 2] = run; run += v2;
    if (base + 3 < n) out[base + 3] = run;
}

__global__ void kScanB(int m) {
    __shared__ int sh[128];
    int t = threadIdx.x;
    int v = (t < m) ? g_part[t] : 0;
    sh[t] = v;
    __syncthreads();
    for (int off = 1; off < 128; off <<= 1) {
        int x = (t >= off) ? sh[t - off] : 0;
        __syncthreads();
        sh[t] += x;
        __syncthreads();
    }
    if (t < m) g_part[t] = sh[t] - v;
    if (t == 0) g_part[m] = sh[m - 1 < 0 ? 0 : m - 1];
}

__global__ void kScanC(int* __restrict__ out, int n, int m) {
    int i = blockIdx.x * blockDim.x + threadIdx.x;
    if (i < n) out[i] += g_part[i >> 10];
    else if (i == n) out[n] = g_part[m];
}

__global__ void kInitCur() {
    int i = blockIdx.x * blockDim.x + threadIdx.x;
    if (i >= NN) return;
    g_curD[i] = g_rowD[i];
    g_curS[i] = g_rowS[i];
}

__global__ void kFill(const int* __restrict__ ei, const float* __restrict__ ew) {
    int e = blockIdx.x * blockDim.x + threadIdx.x;
    if (e >= NE) return;
    int s = ei[e], d = ei[NE + e];
    float w = ew[e];
    int p = atomicAdd(&g_curD[d], 1);
    g_colD[p] = s;
    g_ewD[p] = w;
    int q = atomicAdd(&g_curS[s], 1);
    g_colS[q] = d;
    int r = atomicAdd(&g_curS[d], 1);
    g_colS[r] = s;
}

// ---------------- position aggregation (layer-invariant) --------------------
__global__ void kAggP(const int* __restrict__ ei, const float* __restrict__ ew,
                      const float* __restrict__ pos) {
    int e = blockIdx.x * blockDim.x + threadIdx.x;
    if (e >= NE) return;
    int s = ei[e], d = ei[NE + e];
    float w = ew[e];
#pragma unroll
    for (int p = 0; p < 3; p++)
        atomicAdd(&g_aggp[d * 3 + p], w * (pos[s * 3 + p] - pos[d * 3 + p]));
}

// ---------------- feature aggregation: warp per node, float4 lanes ----------
__global__ void kAggX(const float* __restrict__ x) {
    int u = blockIdx.x * 8 + (threadIdx.x >> 5);
    int lane = threadIdx.x & 31;
    if (u >= NN) return;
    int b = g_rowD[u], e = g_rowD[u + 1];
    float4 acc = make_float4(0.f, 0.f, 0.f, 0.f);
    int t = b;
    for (; t + 1 < e; t += 2) {
        int s0 = g_colD[t], s1 = g_colD[t + 1];
        float w0 = g_ewD[t], w1 = g_ewD[t + 1];
        float4 v0 = __ldg(&((const float4*)x)[s0 * 32 + lane]);
        float4 v1 = __ldg(&((const float4*)x)[s1 * 32 + lane]);
        acc.x += w0 * v0.x + w1 * v1.x;
        acc.y += w0 * v0.y + w1 * v1.y;
        acc.z += w0 * v0.z + w1 * v1.z;
        acc.w += w0 * v0.w + w1 * v1.w;
    }
    if (t < e) {
        int s0 = g_colD[t];
        float w0 = g_ewD[t];
        float4 v0 = __ldg(&((const float4*)x)[s0 * 32 + lane]);
        acc.x += w0 * v0.x; acc.y += w0 * v0.y; acc.z += w0 * v0.z; acc.w += w0 * v0.w;
    }
    ((float4*)g_aggx)[u * 32 + lane] = acc;
}

// ---------------- fused dual-GEMM + pos + bias (128x128 tile, 8x8/thread) ---
// (proven R2 version — plain fp32 FFMA)
__global__ void kGemm(const float* __restrict__ A1, const float* __restrict__ A2,
                      const float* __restrict__ W1, const float* __restrict__ W2,
                      const float* __restrict__ Wp, const float* __restrict__ bias,
                      float* __restrict__ out) {
    __shared__ float As[16][132];   // [k][row], padded
    __shared__ float Bs[16][128];   // [k][col]
    int tid = threadIdx.x;
    int tx = tid & 15, ty = tid >> 4;   // 16x16 threads
    int rowBase = blockIdx.x * 128;
    float acc[8][8];
#pragma unroll
    for (int i = 0; i < 8; i++)
#pragma unroll
        for (int j = 0; j < 8; j++) acc[i][j] = 0.f;

    for (int m = 0; m < 2; m++) {
        const float* A = m ? A2 : A1;
        const float* W = m ? W2 : W1;
        for (int kb = 0; kb < 128; kb += 16) {
            // load A tile transposed: 128 rows x 16 k
#pragma unroll
            for (int i = 0; i < 2; i++) {
                int idx = tid + i * 256;        // 0..511 float4 slots
                int r = idx >> 2;               // row 0..127
                int k4 = idx & 3;               // which float4 of the 16 k
                int row = rowBase + r;
                float4 v = (row < NN) ? ((const float4*)A)[row * 32 + (kb >> 2) + k4]
                                      : make_float4(0.f, 0.f, 0.f, 0.f);
                As[k4 * 4 + 0][r] = v.x;
                As[k4 * 4 + 1][r] = v.y;
                As[k4 * 4 + 2][r] = v.z;
                As[k4 * 4 + 3][r] = v.w;
            }
            // load B tile: 16 k-rows x 128 cols
#pragma unroll
            for (int i = 0; i < 2; i++) {
                int idx = tid + i * 256;
                int r = idx >> 5;               // k-row 0..15
                int c4 = idx & 31;
                ((float4*)&Bs[r][0])[c4] = ((const float4*)W)[(kb + r) * 32 + c4];
            }
            __syncthreads();
#pragma unroll
            for (int k = 0; k < 16; k++) {
                float4 a0 = ((float4*)&As[k][ty * 8])[0];
                float4 a1 = ((float4*)&As[k][ty * 8])[1];
                float4 b0 = ((float4*)&Bs[k][tx * 8])[0];
                float4 b1 = ((float4*)&Bs[k][tx * 8])[1];
                float av[8] = {a0.x, a0.y, a0.z, a0.w, a1.x, a1.y, a1.z, a1.w};
                float bv[8] = {b0.x, b0.y, b0.z, b0.w, b1.x, b1.y, b1.z, b1.w};
#pragma unroll
                for (int i = 0; i < 8; i++)
#pragma unroll
                    for (int j = 0; j < 8; j++) acc[i][j] += av[i] * bv[j];
            }
            __syncthreads();
        }
    }
#pragma unroll
    for (int i = 0; i < 8; i++) {
        int row = rowBase + ty * 8 + i;
        if (row >= NN) continue;
        float p0 = g_aggp[row * 3 + 0];
        float p1 = g_aggp[row * 3 + 1];
        float p2 = g_aggp[row * 3 + 2];
#pragma unroll
        for (int j = 0; j < 8; j++) {
            int col = tx * 8 + j;
            float v = acc[i][j] + p0 * Wp[col] + p1 * Wp[CC + col] + p2 * Wp[2 * CC + col]
                      + bias[col];
            out[row * CC + col] = v;
        }
    }
}

// ---------------- batch-norm ------------------------------------------------
__global__ void kColSum(const float* __restrict__ pre) {
    int c = threadIdx.x;
    int rowBase = blockIdx.x * 512;
    int rowEnd = min(rowBase + 512, NN);
    float s = 0.f, q = 0.f;
    for (int r = rowBase; r < rowEnd; r++) {
        float v = pre[r * CC + c];
        s += v;
        q += v * v;
    }
    atomicAdd(&g_sum[c], (double)s);
    atomicAdd(&g_sq[c], (double)q);
}

__global__ void kBnFinal(const float* __restrict__ g, const float* __restrict__ be) {
    int c = threadIdx.x;
    double mu = g_sum[c] / (double)NN;
    double var = g_sq[c] / (double)NN - mu * mu;
    float sc = (float)((double)g[c] / sqrt(var + (double)EPS));
    g_bns[c] = sc;
    g_bnt[c] = be[c] - (float)mu * sc;
}

__global__ void kBnRelu(float* __restrict__ pre) {
    int idx = blockIdx.x * blockDim.x + threadIdx.x;
    if (idx >= NN * CC) return;
    int c = idx & (CC - 1);
    float v = pre[idx] * g_bns[c] + g_bnt[c];
    pre[idx] = v > 0.f ? v : 0.f;
}

// ---------------- score + ranking -------------------------------------------
__global__ void kScore(const float* __restrict__ h, const float* __restrict__ w) {
    int gw = (blockIdx.x * blockDim.x + threadIdx.x) >> 5;
    int lane = threadIdx.x & 31;
    if (gw >= NN) return;
    float acc = 0.f;
    for (int c = lane; c < CC; c += 32) acc += h[gw * CC + c] * w[c];
#pragma unroll
    for (int o = 16; o; o >>= 1) acc += __shfl_down_sync(0xffffffffu, acc, o);
    if (lane == 0) g_score[gw] = acc;
}

__global__ void kKeyHist() {
    int i = blockIdx.x * blockDim.x + threadIdx.x;
    if (i >= NN) return;
    unsigned u = __float_as_uint(g_score[i]);
    u = (u & 0x80000000u) ? ~u : (u | 0x80000000u);
    g_key[i] = u;
    atomicAdd(&g_hist[u >> 16], 1);
}

__global__ void kBucketFill() {
    int i = blockIdx.x * blockDim.x + threadIdx.x;
    if (i >= NN) return;
    unsigned k = g_key[i];
    int hi = k >> 16;
    int p = g_base[hi] + atomicAdd(&g_bcur[hi], 1);
    g_bkey[p] = k;
}

__global__ void kRank() {
    int i = blockIdx.x * blockDim.x + threadIdx.x;
    if (i >= NN) return;
    unsigned k = g_key[i];
    int hi = k >> 16;
    int s = g_base[hi], e = g_base[hi + 1];
    int c = 0;
    for (int t = s; t < e; t++) c += (g_bkey[t] < k) ? 1 : 0;
    g_rank[i] = 1 + s + c;
}

// ---------------- MIS: persistent kernel with frontier ----------------------
__global__ void kMisInit() {
    int i = blockIdx.x * blockDim.x + threadIdx.x;
    if (i >= NN) return;
    g_arank[i] = g_rank[i];
    g_fr[0][i] = i;
    if (i == 0) { g_fc[0] = NN; g_fc[1] = 0; }
}

__device__ __forceinline__ void gridBar() {
    __syncthreads();
    if (threadIdx.x == 0) {
        __threadfence();
        unsigned gen = g_barGen;
        unsigned t = atomicAdd(&g_barCnt, 1);
        if (t == PBLK - 1) {
            g_barCnt = 0;
            __threadfence();
            atomicAdd(&g_barGen, 1);
        } else {
            while (*(volatile unsigned*)&g_barGen == gen) {}
            __threadfence();
        }
    }
    __syncthreads();
}

__global__ void kMisPersist() {
    int tid = threadIdx.x;
    int gw = (blockIdx.x * 256 + tid) >> 5;
    int lane = tid & 31;
    const int nw = (PBLK * 256) >> 5;
    int p = 0;
    for (int it = 0; it < 32; it++) {
        int fc = g_fc[p];
        if (fc == 0) break;   // fixpoint: remaining iterations are no-ops
        // phase A: compute sel over frontier
        for (int i = gw; i < fc; i += nw) {
            int u = g_fr[p][i];
            int au = g_arank[u];
            int b = g_rowS[u], e = g_rowS[u + 1];
            int nmax = -1;
            for (int t = b + lane; t < e; t += 32)
                nmax = max(nmax, g_arank[g_colS[t]]);
#pragma unroll
            for (int o = 16; o; o >>= 1)
                nmax = max(nmax, __shfl_xor_sync(0xffffffffu, nmax, o));
            if (lane == 0) g_sel[u] = (au > nmax) ? 1 : 0;
        }
        gridBar();
        // phase B: commit, drop neighbors, build next frontier
        for (int i = gw; i < fc; i += nw) {
            int u = g_fr[p][i];
            if (g_sel[u]) {
                if (lane == 0) { g_mis[u] = 1; g_arank[u] = -1; }
                continue;
            }
            int b = g_rowS[u], e = g_rowS[u + 1];
            int f = 0;
            for (int t = b + lane; t < e; t += 32) f |= g_sel[g_colS[t]];
            unsigned any = __ballot_sync(0xffffffffu, f != 0);
            if (lane == 0) {
                if (any) g_arank[u] = -1;
                else {
                    int pos = atomicAdd(&g_fc[1 - p], 1);
                    g_fr[1 - p][pos] = u;
                }
            }
        }
        gridBar();
        if (blockIdx.x == 0 && tid == 0) g_fc[p] = 0;
        p ^= 1;
    }
}

__global__ void kCluster() {
    int u = (blockIdx.x * blockDim.x + threadIdx.x) >> 5;
    int lane = threadIdx.x & 31;
    if (u >= NN) return;
    int b = g_rowS[u], e = g_rowS[u + 1];
    int bm = -1, arg = -1;
    for (int t = b + lane; t < e; t += 32) {
        int j = g_colS[t];
        if (g_mis[j]) {
            int r = g_rank[j];
            if (r > bm) { bm = r; arg = j; }
        }
    }
#pragma unroll
    for (int o = 16; o; o >>= 1) {
        int obm = __shfl_down_sync(0xffffffffu, bm, o);
        int oarg = __shfl_down_sync(0xffffffffu, arg, o);
        if (obm > bm) { bm = obm; arg = oarg; }
    }
    if (lane == 0) g_cluster[u] = g_mis[u] ? u : (arg >= 0 ? arg : u);
}

// ---------------- pooling + outputs -----------------------------------------
__global__ void kPoolScatter() {
    int idx = blockIdx.x * blockDim.x + threadIdx.x;
    if (idx >= NN * CC) return;
    int i = idx >> 7, c = idx & 127;
    float v = g_h1[idx];
    int t = g_cluster[i];
    atomicMax((int*)&g_pool[t * CC + c], __float_as_int(v));
}

__global__ void kOutX(float* __restrict__ out, int osz) {
    int idx = blockIdx.x * blockDim.x + threadIdx.x;
    if (idx >= NN * CC) return;
    float v = g_mis[idx >> 7] ? g_pool[idx] : 0.f;
    if (idx < osz) out[idx] = v;
}

__global__ void kOutEdge(const int* __restrict__ ei, float* __restrict__ out, int osz) {
    int e = blockIdx.x * blockDim.x + threadIdx.x;
    if (e >= NE) return;
    int o1 = NN * CC + e, o2 = NN * CC + NE + e;
    if (o1 < osz) out[o1] = (float)g_cluster[ei[e]];
    if (o2 < osz) out[o2] = (float)g_cluster[ei[NE + e]];
}

__global__ void kOutTail(const float* __restrict__ ew, const float* __restrict__ pos,
                         const int* __restrict__ batch, float* __restrict__ out, int osz) {
    int idx = blockIdx.x * blockDim.x + threadIdx.x;
    const int b0 = NN * CC + 2 * NE;
    const int b1 = b0 + NE;
    const int b2 = b1 + NN * 3;
    const int b3 = b2 + NN;
    if (idx < NE && b0 + idx < osz) out[b0 + idx] = ew[idx];
    if (idx < NN * 3 && b1 + idx < osz) out[b1 + idx] = g_mis[idx / 3] ? pos[idx] : 0.f;
    if (idx < NN && b2 + idx < osz) out[b2 + idx] = (float)batch[idx];
    if (idx < NN && b3 + idx < osz) out[b3 + idx] = g_mis[idx] ? 1.f : 0.f;
}

// ---------------- helper ----------------------------------------------------
static void runScan(const int* in, int* out, int n) {
    int m = (n + 1023) / 1024;
    kScanA<<<m, 256>>>(in, out, n);
    kScanB<<<1, 128>>>(m);
    kScanC<<<(n + 256) / 256, 256>>>(out, n, m);
}

// ---------------- launch ----------------------------------------------------
extern "C" void kernel_launch(void* const* d_in, const int* in_sizes, int n_in,
                              void* d_out, int out_size) {
    const float* x     = (const float*)d_in[0];
    const int*   ei    = (const int*)d_in[1];
    const float* ew    = (const float*)d_in[2];
    const float* pos   = (const float*)d_in[3];
    const int*   batch = (const int*)d_in[4];
    const float* Wr0 = (const float*)d_in[5];
    const float* Wm0 = (const float*)d_in[6];
    const float* Wp0 = (const float*)d_in[7];
    const float* b0  = (const float*)d_in[8];
    const float* g0  = (const float*)d_in[9];
    const float* be0 = (const float*)d_in[10];
    const float* Wr1 = (const float*)d_in[11];
    const float* Wm1 = (const float*)d_in[12];
    const float* Wp1 = (const float*)d_in[13];
    const float* b1  = (const float*)d_in[14];
    const float* g1  = (const float*)d_in[15];
    const float* be1 = (const float*)d_in[16];
    const float* wsc = (const float*)d_in[17];
    float* out = (float*)d_out;

    void *p_curD, *p_curS, *p_rowD, *p_rowS, *p_aggp, *p_hist, *p_base, *p_bcur,
         *p_mis, *p_sel, *p_pool, *p_sum, *p_sq, *p_h0, *p_h1, *p_aggx,
         *p_barG, *p_barC;
    cudaGetSymbolAddress(&p_curD, g_curD);
    cudaGetSymbolAddress(&p_curS, g_curS);
    cudaGetSymbolAddress(&p_rowD, g_rowD);
    cudaGetSymbolAddress(&p_rowS, g_rowS);
    cudaGetSymbolAddress(&p_aggp, g_aggp);
    cudaGetSymbolAddress(&p_hist, g_hist);
    cudaGetSymbolAddress(&p_base, g_base);
    cudaGetSymbolAddress(&p_bcur, g_bcur);
    cudaGetSymbolAddress(&p_mis,  g_mis);
    cudaGetSymbolAddress(&p_sel,  g_sel);
    cudaGetSymbolAddress(&p_pool, g_pool);
    cudaGetSymbolAddress(&p_sum,  g_sum);
    cudaGetSymbolAddress(&p_sq,   g_sq);
    cudaGetSymbolAddress(&p_h0,   g_h0);
    cudaGetSymbolAddress(&p_h1,   g_h1);
    cudaGetSymbolAddress(&p_aggx, g_aggx);
    cudaGetSymbolAddress(&p_barG, g_barGen);
    cudaGetSymbolAddress(&p_barC, g_barCnt);
    float* h0 = (float*)p_h0;
    float* h1 = (float*)p_h1;

    const int EB = (NE + 255) / 256;
    const int NB = (NN + 255) / 256;
    const int WB = (NN * 32 + 255) / 256;
    const int XB = (NN * CC + 255) / 256;
    const int GB = (NN + 127) / 128;
    const int AB = (NN + 7) / 8;

    // ---- CSR build ----
    cudaMemsetAsync(p_curD, 0, NN * sizeof(int));
    cudaMemsetAsync(p_curS, 0, NN * sizeof(int));
    kCountDeg<<<EB, 256>>>(ei);
    runScan((const int*)p_curD, (int*)p_rowD, NN);
    runScan((const int*)p_curS, (int*)p_rowS, NN);
    kInitCur<<<NB, 256>>>();
    kFill<<<EB, 256>>>(ei, ew);

    // ---- pos aggregation ----
    cudaMemsetAsync(p_aggp, 0, NN * 3 * sizeof(float));
    kAggP<<<EB, 256>>>(ei, ew, pos);

    // ---- layer 0 ----
    kAggX<<<AB, 256>>>(x);
    kGemm<<<GB, 256>>>(x, (const float*)p_aggx, Wr0, Wm0, Wp0, b0, h0);
    cudaMemsetAsync(p_sum, 0, CC * sizeof(double));
    cudaMemsetAsync(p_sq, 0, CC * sizeof(double));
    kColSum<<<(NN + 511) / 512, CC>>>(h0);
    kBnFinal<<<1, CC>>>(g0, be0);
    kBnRelu<<<XB, 256>>>(h0);

    // ---- layer 1 ----
    kAggX<<<AB, 256>>>(h0);
    kGemm<<<GB, 256>>>(h0, (const float*)p_aggx, Wr1, Wm1, Wp1, b1, h1);
    cudaMemsetAsync(p_sum, 0, CC * sizeof(double));
    cudaMemsetAsync(p_sq, 0, CC * sizeof(double));
    kColSum<<<(NN + 511) / 512, CC>>>(h1);
    kBnFinal<<<1, CC>>>(g1, be1);
    kBnRelu<<<XB, 256>>>(h1);

    // ---- score -> unique ranks ----
    kScore<<<(NN * 32 + 255) / 256, 256>>>(h1, wsc);
    cudaMemsetAsync(p_hist, 0, HB * sizeof(int));
    kKeyHist<<<NB, 256>>>();
    runScan((const int*)p_hist, (int*)p_base, HB);
    cudaMemsetAsync(p_bcur, 0, HB * sizeof(int));
    kBucketFill<<<NB, 256>>>();
    kRank<<<NB, 256>>>();

    // ---- MIS (persistent kernel, frontier-compacted) ----
    cudaMemsetAsync(p_mis, 0, NN);
    cudaMemsetAsync(p_sel, 0, NN);
    cudaMemsetAsync(p_barG, 0, sizeof(unsigned));
    cudaMemsetAsync(p_barC, 0, sizeof(unsigned));
    kMisInit<<<NB, 256>>>();
    kMisPersist<<<PBLK, 256>>>();
    kCluster<<<WB, 256>>>();

    // ---- pooling + outputs ----
    cudaMemsetAsync(p_pool, 0, NN * CC * sizeof(float));
    kPoolScatter<<<XB, 256>>>();
    kOutX<<<XB, 256>>>(out, out_size);
    kOutEdge<<<EB, 256>>>(ei, out, out_size);
    kOutTail<<<EB, 256>>>(ew, pos, batch, out, out_size);
}